// round 16
// baseline (speedup 1.0000x reference)
#include <cuda_runtime.h>
#include <cstdint>

// LmulLinear: out[m,p] = sum_k bitcast_f32(bits(x[m,k]) + bits(w[p,k]) - OFFSET) + bias[p]
// M=256, K=512, P=512.
//
// R16: R15 (classic-SGEMM, k-major smem, 4x4 microtile, reg double-buffer)
//      with FIXED 16B-aligned row strides (SRA=132, SRB=68 words).

#define M_DIM 256
#define K_DIM 512
#define P_DIM 512
#define BM 128
#define BN 64
#define KSPLIT 8
#define KG (K_DIM / KSPLIT)     // 64 k per CTA
#define SRA (BM + 4)            // 132 words = 528 B (16B multiple; mod 32 = 4)
#define SRB (BN + 4)            // 68 words = 272 B (16B multiple)
#define A_WORDS ((KG + 1) * SRA)   // +1 row: k+1 prefetch at k=KG-1 stays in bounds
#define B_WORDS ((KG + 1) * SRB)
#define SMEM_BYTES ((A_WORDS + B_WORDS) * 4)   // ~52 KB

__device__ float g_partial[KSPLIT * M_DIM * P_DIM];   // 4 MB, L2-resident

static __device__ __forceinline__ float u2f(uint32_t u) { return __uint_as_float(u); }

extern __shared__ uint32_t smem[];

__global__ void __launch_bounds__(512)
lmul_partial_kernel(const float* __restrict__ x,
                    const float* __restrict__ w)
{
    constexpr uint32_t OFFSET = 1064828928u;  // 0x3F780000

    uint32_t* As = smem;             // [KG+1][SRA]  As[k][m]
    uint32_t* Bs = smem + A_WORDS;   // [KG+1][SRB]  Bs[k][p], offset-folded

    const int tid = threadIdx.x;
    const int tx  = tid & 15;        // p quad: cols p0 + tx*4 .. +3
    const int ty  = tid >> 4;        // m quad: rows m0 + ty*4 .. +3  (ty < 32)
    const int m0  = blockIdx.y * BM;
    const int p0  = blockIdx.x * BN;
    const int kbase = blockIdx.z * KG;

    const uint32_t* __restrict__ xu = reinterpret_cast<const uint32_t*>(x);
    const uint32_t* __restrict__ wu = reinterpret_cast<const uint32_t*>(w);

    // ---- load A tile transposed: x[m0+row][kbase+k] -> As[k][row] ----
    #pragma unroll
    for (int i = 0; i < 4; i++) {
        int idx = tid + i * 512;       // 0..2047
        int row = idx >> 4;            // 0..127
        int c4  = idx & 15;            // k-quad index
        uint4 v = *reinterpret_cast<const uint4*>(&xu[(m0 + row) * K_DIM + kbase + c4 * 4]);
        As[(c4 * 4 + 0) * SRA + row] = v.x;
        As[(c4 * 4 + 1) * SRA + row] = v.y;
        As[(c4 * 4 + 2) * SRA + row] = v.z;
        As[(c4 * 4 + 3) * SRA + row] = v.w;
    }
    // ---- load B tile transposed + offset-folded ----
    #pragma unroll
    for (int i = 0; i < 2; i++) {
        int idx = tid + i * 512;       // 0..1023
        int row = idx >> 4;            // 0..63
        int c4  = idx & 15;
        uint4 v = *reinterpret_cast<const uint4*>(&wu[(p0 + row) * K_DIM + kbase + c4 * 4]);
        Bs[(c4 * 4 + 0) * SRB + row] = v.x - OFFSET;
        Bs[(c4 * 4 + 1) * SRB + row] = v.y - OFFSET;
        Bs[(c4 * 4 + 2) * SRB + row] = v.z - OFFSET;
        Bs[(c4 * 4 + 3) * SRB + row] = v.w - OFFSET;
    }
    // zero the prefetch-overrun row (k = KG); values loaded but never used
    for (int i = tid; i < SRA; i += 512) As[KG * SRA + i] = 0;
    for (int i = tid; i < SRB; i += 512) Bs[KG * SRB + i] = 0;
    __syncthreads();

    // ---- main loop: 4x4 microtile, k-major, register double-buffered ----
    const uint32_t* Ab = As + ty * 4;   // + k*SRA (always 16B aligned: ty*4 and SRA mult of 4)
    const uint32_t* Bb = Bs + tx * 4;   // + k*SRB

    float acc[4][4];
    #pragma unroll
    for (int r = 0; r < 4; r++)
        #pragma unroll
        for (int c = 0; c < 4; c++) acc[r][c] = 0.f;

    uint4 a = *reinterpret_cast<const uint4*>(Ab);
    uint4 b = *reinterpret_cast<const uint4*>(Bb);

    #pragma unroll 4
    for (int k = 0; k < KG; k++) {
        uint4 an = *reinterpret_cast<const uint4*>(Ab + (k + 1) * SRA);
        uint4 bn = *reinterpret_cast<const uint4*>(Bb + (k + 1) * SRB);

        const uint32_t av[4] = {a.x, a.y, a.z, a.w};
        const uint32_t bv[4] = {b.x, b.y, b.z, b.w};
        #pragma unroll
        for (int r = 0; r < 4; r++)
            #pragma unroll
            for (int c = 0; c < 4; c++)
                acc[r][c] += u2f(av[r] + bv[c]);

        a = an; b = bn;
    }

    // ---- write partials (coalesced 256B runs), skip L1 ----
    float* part = g_partial + blockIdx.z * (M_DIM * P_DIM);
    #pragma unroll
    for (int r = 0; r < 4; r++) {
        const int m = m0 + ty * 4 + r;
        float4 v = make_float4(acc[r][0], acc[r][1], acc[r][2], acc[r][3]);
        __stcg(reinterpret_cast<float4*>(&part[m * P_DIM + p0 + tx * 4]), v);
    }
}

__global__ void __launch_bounds__(128)
lmul_reduce_kernel(const float* __restrict__ bias,
                   float* __restrict__ out)
{
    // 32768 float4 outputs; 256 CTAs x 128 threads, one float4 each, MLP=9.
    const int idx4 = blockIdx.x * 128 + threadIdx.x;
    const int base = idx4 * 4;
    const int p = base & (P_DIM - 1);

    float4 v[KSPLIT];
    #pragma unroll
    for (int k = 0; k < KSPLIT; k++)
        v[k] = __ldcg(reinterpret_cast<const float4*>(g_partial + k * (M_DIM * P_DIM) + base));
    float4 b = __ldg(reinterpret_cast<const float4*>(bias + p));

    float4 r = v[0];
    #pragma unroll
    for (int k = 1; k < KSPLIT; k++) {
        r.x += v[k].x; r.y += v[k].y; r.z += v[k].z; r.w += v[k].w;
    }
    r.x += b.x; r.y += b.y; r.z += b.z; r.w += b.w;

    *reinterpret_cast<float4*>(out + base) = r;
}

extern "C" void kernel_launch(void* const* d_in, const int* in_sizes, int n_in,
                              void* d_out, int out_size)
{
    const float* x    = (const float*)d_in[0];   // (256, 512)
    const float* w    = (const float*)d_in[1];   // (512, 512)
    const float* bias = (const float*)d_in[2];   // (512,)
    float* out = (float*)d_out;                  // (256, 512)

    cudaFuncSetAttribute(lmul_partial_kernel,
                         cudaFuncAttributeMaxDynamicSharedMemorySize, SMEM_BYTES);

    dim3 grid1(P_DIM / BN, M_DIM / BM, KSPLIT);  // (8, 2, 8) = 128 CTAs
    lmul_partial_kernel<<<grid1, 512, SMEM_BYTES>>>(x, w);

    dim3 grid2((M_DIM * P_DIM) / (128 * 4));     // 256 CTAs
    lmul_reduce_kernel<<<grid2, 128>>>(bias, out);
}

// round 17
// speedup vs baseline: 1.0022x; 1.0022x over previous
#include <cuda_runtime.h>
#include <cstdint>

// LmulLinear: out[m,p] = sum_k bitcast_f32(bits(x[m,k]) + bits(w[p,k]) - OFFSET) + bias[p]
// M=256, K=512, P=512.
//
// R17: init kernel (out = bias) + GEMM with red.global.add.v4.f32 epilogue.
//      No partials scratch, no reduce kernel, no fences. 1024 CTAs x 128 thr,
//      BM=BN=32, KSPLIT=8, k-major smem, 2x4 microtile (2.25 issues/MAC).

#define M_DIM 256
#define K_DIM 512
#define P_DIM 512
#define BM 32
#define BN 32
#define KSPLIT 8
#define KG (K_DIM / KSPLIT)     // 64 k per CTA
#define SRA 36                  // k-major row stride (BM+4 words; mult of 4, mod 32 = 4)
#define A_WORDS (KG * SRA)      // 2304 words
#define B_WORDS (KG * SRA)      // same shape for B (BN = BM = 32)

static __device__ __forceinline__ float u2f(uint32_t u) { return __uint_as_float(u); }

__global__ void __launch_bounds__(256)
lmul_init_kernel(const float* __restrict__ bias,
                 float* __restrict__ out)
{
    // out[m][p] = bias[p]; 32768 float4 stores, 128 CTAs x 256 thr.
    const int idx4 = blockIdx.x * 256 + threadIdx.x;
    const int base = idx4 * 4;
    const int p = base & (P_DIM - 1);
    float4 b = *reinterpret_cast<const float4*>(bias + p);
    *reinterpret_cast<float4*>(out + base) = b;
}

__global__ void __launch_bounds__(128)
lmul_gemm_red_kernel(const float* __restrict__ x,
                     const float* __restrict__ w,
                     float* __restrict__ out)
{
    constexpr uint32_t OFFSET = 1064828928u;  // 0x3F780000

    __shared__ uint32_t As[A_WORDS];   // As[k][m], k-major
    __shared__ uint32_t Bs[B_WORDS];   // Bs[k][p], k-major, offset-folded

    const int tid = threadIdx.x;
    const int tx  = tid & 7;         // p quad: cols p0 + 4*tx .. +3
    const int ty  = tid >> 3;        // m pair: rows m0 + 2*ty, +1   (ty < 16)
    const int m0  = blockIdx.y * BM;
    const int p0  = blockIdx.x * BN;
    const int kbase = blockIdx.z * KG;

    const uint32_t* __restrict__ xu = reinterpret_cast<const uint32_t*>(x);
    const uint32_t* __restrict__ wu = reinterpret_cast<const uint32_t*>(w);

    // ---- load tiles transposed to k-major: 32 rows x 16 uint4 each; 4/thread ----
    #pragma unroll
    for (int i = 0; i < 4; i++) {
        int idx = tid + i * 128;       // 0..511
        int row = idx >> 4;            // 0..31
        int c4  = idx & 15;            // k-quad
        uint4 va = *reinterpret_cast<const uint4*>(&xu[(m0 + row) * K_DIM + kbase + c4 * 4]);
        As[(c4 * 4 + 0) * SRA + row] = va.x;
        As[(c4 * 4 + 1) * SRA + row] = va.y;
        As[(c4 * 4 + 2) * SRA + row] = va.z;
        As[(c4 * 4 + 3) * SRA + row] = va.w;
        uint4 vb = *reinterpret_cast<const uint4*>(&wu[(p0 + row) * K_DIM + kbase + c4 * 4]);
        Bs[(c4 * 4 + 0) * SRA + row] = vb.x - OFFSET;
        Bs[(c4 * 4 + 1) * SRA + row] = vb.y - OFFSET;
        Bs[(c4 * 4 + 2) * SRA + row] = vb.z - OFFSET;
        Bs[(c4 * 4 + 3) * SRA + row] = vb.w - OFFSET;
    }
    __syncthreads();

    // ---- main loop: per k, LDS.64 a-pair + LDS.128 b-quad, 8 MACs ----
    const uint32_t* Ab = As + ty * 2;   // + k*SRA ; 8B aligned
    const uint32_t* Bb = Bs + tx * 4;   // + k*SRA ; 16B aligned

    float acc[2][4];
    #pragma unroll
    for (int r = 0; r < 2; r++)
        #pragma unroll
        for (int c = 0; c < 4; c++) acc[r][c] = 0.f;

    #pragma unroll 8
    for (int k = 0; k < KG; k++) {
        uint2 a = *reinterpret_cast<const uint2*>(Ab + k * SRA);
        uint4 b = *reinterpret_cast<const uint4*>(Bb + k * SRA);

        acc[0][0] += u2f(a.x + b.x);
        acc[0][1] += u2f(a.x + b.y);
        acc[0][2] += u2f(a.x + b.z);
        acc[0][3] += u2f(a.x + b.w);
        acc[1][0] += u2f(a.y + b.x);
        acc[1][1] += u2f(a.y + b.y);
        acc[1][2] += u2f(a.y + b.z);
        acc[1][3] += u2f(a.y + b.w);
    }

    // ---- epilogue: vectorized reduction-add into out (init'd to bias) ----
    #pragma unroll
    for (int r = 0; r < 2; r++) {
        float* dst = out + (m0 + 2 * ty + r) * P_DIM + p0 + 4 * tx;
        asm volatile("red.global.add.v4.f32 [%0], {%1, %2, %3, %4};"
                     :: "l"(dst),
                        "f"(acc[r][0]), "f"(acc[r][1]), "f"(acc[r][2]), "f"(acc[r][3])
                     : "memory");
    }
}

extern "C" void kernel_launch(void* const* d_in, const int* in_sizes, int n_in,
                              void* d_out, int out_size)
{
    const float* x    = (const float*)d_in[0];   // (256, 512)
    const float* w    = (const float*)d_in[1];   // (512, 512)
    const float* bias = (const float*)d_in[2];   // (512,)
    float* out = (float*)d_out;                  // (256, 512)

    // 1) out = bias (stream-ordered before the GEMM's reduction-adds)
    lmul_init_kernel<<<(M_DIM * P_DIM) / (256 * 4), 256>>>(bias, out);

    // 2) GEMM, accumulating into out via red.global.add
    dim3 grid(P_DIM / BN, M_DIM / BM, KSPLIT);   // (16, 8, 8) = 1024 CTAs
    lmul_gemm_red_kernel<<<grid, 128>>>(x, w, out);
}